// round 8
// baseline (speedup 1.0000x reference)
#include <cuda_runtime.h>
#include <cuda_fp16.h>
#include <cstdint>

#define D 128
#define NG 64
#define CO 16
#define MAXN 50176
#define MAXE 600064
#define NEG 0.1f
#define AST 132   // padded smem row stride (floats)

// -------- scratch (device globals: allocation-free workaround) --------
__device__ float  g_h1[MAXN * D];
__device__ float  g_h2[MAXN * D];
__device__ __half g_hh[MAXN * D];     // fp16 copy of GEMM output for gathers
__device__ float  g_BH1[D * D];
__device__ float  g_BL1[D * D];
__device__ float  g_BH2[D * D];
__device__ float  g_BL2[D * D];
__device__ float  g_dinv[MAXN];
__device__ int    g_degi[MAXN];
__device__ int    g_rowptr[MAXN + 1];
__device__ int    g_fill[MAXN];
__device__ int    g_csr_src[MAXE];
__device__ int    g_bpub[64];         // decoupled-lookback publications (total+1)
__device__ float  g_pool[NG * D];
__device__ float  g_cnt[NG];

__device__ __forceinline__ float lrelu(float v) {
    return v >= 0.0f ? v : NEG * v;
}
__device__ __forceinline__ uint32_t tf32bits(float x) {
    uint32_t u;
    asm("cvt.rna.tf32.f32 %0, %1;" : "=r"(u) : "f"(x));
    return u;
}
__device__ __forceinline__ void mma8(float* c, const uint32_t* a, uint32_t b0, uint32_t b1) {
    asm volatile(
        "mma.sync.aligned.m16n8k8.row.col.f32.tf32.tf32.f32 "
        "{%0,%1,%2,%3}, {%4,%5,%6,%7}, {%8,%9}, {%0,%1,%2,%3};"
        : "+f"(c[0]), "+f"(c[1]), "+f"(c[2]), "+f"(c[3])
        : "r"(a[0]), "r"(a[1]), "r"(a[2]), "r"(a[3]), "r"(b0), "r"(b1));
}

// -------- init: zero degi/pool/cnt/bpub + tf32-split both W's (transposed) -----
__global__ void k_init(const float* __restrict__ W1, const float* __restrict__ W2, int n) {
    int stride = gridDim.x * blockDim.x;
    int i0 = blockIdx.x * blockDim.x + threadIdx.x;
    for (int i = i0; i < n; i += stride) g_degi[i] = 0;
    for (int i = i0; i < NG * D; i += stride) g_pool[i] = 0.0f;
    for (int i = i0; i < NG; i += stride) g_cnt[i] = 0.0f;
    for (int i = i0; i < 64; i += stride) g_bpub[i] = 0;
    for (int i = i0; i < D * D; i += stride) {
        int nn = i >> 7, k = i & 127;
        float w1 = W1[k * D + nn];
        float h1 = __uint_as_float(tf32bits(w1));
        g_BH1[i] = h1;
        g_BL1[i] = __uint_as_float(tf32bits(w1 - h1));
        float w2 = W2[k * D + nn];
        float h2 = __uint_as_float(tf32bits(w2));
        g_BH2[i] = h2;
        g_BL2[i] = __uint_as_float(tf32bits(w2 - h2));
    }
}

// -------- histogram over dst + graph node counts (fused) --------
__global__ void k_hist(const int* __restrict__ dst, const int* __restrict__ batch,
                       int E, int n) {
    int stride = gridDim.x * blockDim.x;
    int i0 = blockIdx.x * blockDim.x + threadIdx.x;
    for (int e = i0; e < E; e += stride)
        atomicAdd(&g_degi[dst[e]], 1);
    for (int i = i0; i < n; i += stride)
        atomicAdd(&g_cnt[batch[i]], 1.0f);
}

// -------- single-kernel scan: decoupled lookback, 1024-elem chunks --------
// All <=49 blocks are co-resident, so polling predecessors is deadlock-free.
__global__ void k_scan(int n, int nblk) {
    __shared__ int sm[1024];
    __shared__ int s_off;
    int t = threadIdx.x, b = blockIdx.x;
    int i = b * 1024 + t;
    int d = (i < n) ? g_degi[i] : 0;
    sm[t] = d;
    __syncthreads();
    #pragma unroll
    for (int off = 1; off < 1024; off <<= 1) {
        int u = (t >= off) ? sm[t - off] : 0;
        __syncthreads();
        sm[t] += u;
        __syncthreads();
    }
    if (t == 0) {
        // publish local total (+1 so 0 is "not yet")
        atomicExch(&g_bpub[b], sm[1023] + 1);
    }
    // warp 0: sum all predecessor totals (poll until published)
    if (t < 32) {
        int acc = 0;
        for (int j = t; j < b; j += 32) {
            int v;
            do { v = atomicAdd(&g_bpub[j], 0); } while (v == 0);
            acc += v - 1;
        }
        #pragma unroll
        for (int off = 16; off; off >>= 1) acc += __shfl_down_sync(~0u, acc, off);
        if (t == 0) s_off = acc;
    }
    __syncthreads();
    int off = s_off;
    if (i < n) {
        int excl = off + sm[t] - d;
        g_rowptr[i] = excl;
        g_fill[i] = excl;
        g_dinv[i] = rsqrtf((float)d + 1.0f);
    }
    if (b == nblk - 1 && t == 1023) g_rowptr[n] = off + sm[1023];
}

// -------- permute edges into CSR (by dst) --------
__global__ void k_permute(const int* __restrict__ src, const int* __restrict__ dst, int E) {
    int stride = gridDim.x * blockDim.x;
    for (int e = blockIdx.x * blockDim.x + threadIdx.x; e < E; e += stride) {
        int d = dst[e];
        int pos = atomicAdd(&g_fill[d], 1);
        g_csr_src[pos] = src[e];
    }
}

// ===================== tf32x3 HMMA GEMM (4m x 2n warp grid) =====================
// out[n,128] = A[n,128] @ W[128,128]; also writes fp16 copy for the gather.
__global__ void __launch_bounds__(256, 1)
k_gemm_mma(const float* __restrict__ A, const float* __restrict__ BhiG,
           const float* __restrict__ BloG, float* __restrict__ out,
           __half* __restrict__ outh, int n) {
    extern __shared__ float sm[];
    float* As = sm;                 // 128 x AST
    float* Bh = sm + 128 * AST;
    float* Bl = Bh + 128 * AST;

    int t = threadIdx.x;
    int r0 = blockIdx.x * 128;
    int rows = n - r0;
    if (rows > 128) rows = 128;

    const float4* A4 = (const float4*)(A + (size_t)r0 * D);
    for (int i = t; i < 128 * 32; i += 256) {
        int row = i >> 5, c4 = i & 31;
        float4 v = (row < rows) ? A4[row * 32 + c4] : make_float4(0.f, 0.f, 0.f, 0.f);
        *(float4*)&As[row * AST + c4 * 4] = v;
        *(float4*)&Bh[row * AST + c4 * 4] = ((const float4*)BhiG)[i];
        *(float4*)&Bl[row * AST + c4 * 4] = ((const float4*)BloG)[i];
    }
    __syncthreads();

    int wid = t >> 5, lane = t & 31;
    int gid = lane >> 2, tig = lane & 3;
    int wm = wid >> 1, wn = wid & 1;

    float acc[2][8][4];
    #pragma unroll
    for (int s = 0; s < 2; s++)
        #pragma unroll
        for (int nt = 0; nt < 8; nt++)
            #pragma unroll
            for (int q = 0; q < 4; q++) acc[s][nt][q] = 0.0f;

    const float* a00 = &As[(wm * 32 + gid) * AST];
    const float* a01 = &As[(wm * 32 + gid + 8) * AST];
    const float* a10 = &As[(wm * 32 + 16 + gid) * AST];
    const float* a11 = &As[(wm * 32 + 24 + gid) * AST];

    #pragma unroll 2
    for (int k8 = 0; k8 < D; k8 += 8) {
        float v0 = a00[k8 + tig], v1 = a01[k8 + tig];
        float v2 = a00[k8 + tig + 4], v3 = a01[k8 + tig + 4];
        float u0 = a10[k8 + tig], u1 = a11[k8 + tig];
        float u2 = a10[k8 + tig + 4], u3 = a11[k8 + tig + 4];
        uint32_t ah0[4], al0[4], ah1[4], al1[4];
        ah0[0] = tf32bits(v0); al0[0] = tf32bits(v0 - __uint_as_float(ah0[0]));
        ah0[1] = tf32bits(v1); al0[1] = tf32bits(v1 - __uint_as_float(ah0[1]));
        ah0[2] = tf32bits(v2); al0[2] = tf32bits(v2 - __uint_as_float(ah0[2]));
        ah0[3] = tf32bits(v3); al0[3] = tf32bits(v3 - __uint_as_float(ah0[3]));
        ah1[0] = tf32bits(u0); al1[0] = tf32bits(u0 - __uint_as_float(ah1[0]));
        ah1[1] = tf32bits(u1); al1[1] = tf32bits(u1 - __uint_as_float(ah1[1]));
        ah1[2] = tf32bits(u2); al1[2] = tf32bits(u2 - __uint_as_float(ah1[2]));
        ah1[3] = tf32bits(u3); al1[3] = tf32bits(u3 - __uint_as_float(ah1[3]));

        #pragma unroll
        for (int nt = 0; nt < 8; nt++) {
            int brow = (wn * 64 + nt * 8 + gid) * AST + k8;
            uint32_t bh0 = __float_as_uint(Bh[brow + tig]);
            uint32_t bh1 = __float_as_uint(Bh[brow + tig + 4]);
            uint32_t bl0 = __float_as_uint(Bl[brow + tig]);
            uint32_t bl1 = __float_as_uint(Bl[brow + tig + 4]);
            mma8(acc[0][nt], ah0, bh0, bh1);
            mma8(acc[0][nt], al0, bh0, bh1);
            mma8(acc[0][nt], ah0, bl0, bl1);
            mma8(acc[1][nt], ah1, bh0, bh1);
            mma8(acc[1][nt], al1, bh0, bh1);
            mma8(acc[1][nt], ah1, bl0, bl1);
        }
    }

    #pragma unroll
    for (int s = 0; s < 2; s++) {
        int m0 = wm * 32 + s * 16 + gid;
        int m1 = m0 + 8;
        float*  o0 = out  + (size_t)(r0 + m0) * D + wn * 64;
        float*  o1 = out  + (size_t)(r0 + m1) * D + wn * 64;
        __half* p0 = outh + (size_t)(r0 + m0) * D + wn * 64;
        __half* p1 = outh + (size_t)(r0 + m1) * D + wn * 64;
        #pragma unroll
        for (int nt = 0; nt < 8; nt++) {
            int c = nt * 8 + tig * 2;
            if (m0 < rows) {
                *(float2*)&o0[c] = make_float2(acc[s][nt][0], acc[s][nt][1]);
                *(__half2*)&p0[c] = __floats2half2_rn(acc[s][nt][0], acc[s][nt][1]);
            }
            if (m1 < rows) {
                *(float2*)&o1[c] = make_float2(acc[s][nt][2], acc[s][nt][3]);
                *(__half2*)&p1[c] = __floats2half2_rn(acc[s][nt][2], acc[s][nt][3]);
            }
        }
    }
}

// ===================== gather (fp16 neighbors) / pool / head =====================
__device__ __forceinline__ void gcn_body(const float* __restrict__ h,
                                         const __half* __restrict__ hh,
                                         const float* __restrict__ bias,
                                         int node, int lane, float4& r) {
    int beg = g_rowptr[node], end = g_rowptr[node + 1];
    float di = g_dinv[node];
    float4 acc = make_float4(0.f, 0.f, 0.f, 0.f);
    int e = beg;
    for (; e + 2 <= end; e += 2) {
        int s0 = g_csr_src[e], s1 = g_csr_src[e + 1];
        float c0 = g_dinv[s0] * di;
        float c1 = g_dinv[s1] * di;
        uint2 q0 = ((const uint2*)(hh + (size_t)s0 * D))[lane];
        uint2 q1 = ((const uint2*)(hh + (size_t)s1 * D))[lane];
        float2 a0 = __half22float2(*(__half2*)&q0.x);
        float2 a1 = __half22float2(*(__half2*)&q0.y);
        float2 b0 = __half22float2(*(__half2*)&q1.x);
        float2 b1 = __half22float2(*(__half2*)&q1.y);
        acc.x += c0 * a0.x + c1 * b0.x;
        acc.y += c0 * a0.y + c1 * b0.y;
        acc.z += c0 * a1.x + c1 * b1.x;
        acc.w += c0 * a1.y + c1 * b1.y;
    }
    if (e < end) {
        int s0 = g_csr_src[e];
        float c0 = g_dinv[s0] * di;
        uint2 q0 = ((const uint2*)(hh + (size_t)s0 * D))[lane];
        float2 a0 = __half22float2(*(__half2*)&q0.x);
        float2 a1 = __half22float2(*(__half2*)&q0.y);
        acc.x += c0 * a0.x; acc.y += c0 * a0.y;
        acc.z += c0 * a1.x; acc.w += c0 * a1.y;
    }
    float4 hv = ((const float4*)(h + (size_t)node * D))[lane];
    float4 b = ((const float4*)bias)[lane];
    float d2 = di * di;
    r.x = lrelu(acc.x + hv.x * d2 + b.x);
    r.y = lrelu(acc.y + hv.y * d2 + b.y);
    r.z = lrelu(acc.z + hv.z * d2 + b.z);
    r.w = lrelu(acc.w + hv.w * d2 + b.w);
}

__global__ void k_gcn(const float* __restrict__ h, const __half* __restrict__ hh,
                      const float* __restrict__ bias, float* __restrict__ out, int n) {
    int node = blockIdx.x * 8 + (threadIdx.x >> 5);
    if (node >= n) return;
    int lane = threadIdx.x & 31;
    float4 r;
    gcn_body(h, hh, bias, node, lane, r);
    ((float4*)(out + (size_t)node * D))[lane] = r;
}

__global__ void k_gcn_pool(const float* __restrict__ h, const __half* __restrict__ hh,
                           const float* __restrict__ bias,
                           const int* __restrict__ batch, int n) {
    int node = blockIdx.x * 8 + (threadIdx.x >> 5);
    if (node >= n) return;
    int lane = threadIdx.x & 31;
    float4 r;
    gcn_body(h, hh, bias, node, lane, r);
    int gid = batch[node];
    atomicAdd(((float4*)g_pool) + gid * 32 + lane, r);
}

__global__ void k_final(const float* __restrict__ Wl, const float* __restrict__ bl,
                        float* __restrict__ out) {
    int t = threadIdx.x;
    int g = t >> 4;
    int c = t & 15;
    float cnt = fmaxf(g_cnt[g], 1.0f);
    float s = 0.0f;
    #pragma unroll 8
    for (int f = 0; f < D; f++)
        s += g_pool[g * D + f] * Wl[f * CO + c];
    out[g * CO + c] = s / cnt + bl[c];
}

extern "C" void kernel_launch(void* const* d_in, const int* in_sizes, int n_in,
                              void* d_out, int out_size) {
    const float* x     = (const float*)d_in[0];
    const int*   ei    = (const int*)d_in[1];
    const int*   batch = (const int*)d_in[2];
    const float* W1    = (const float*)d_in[3];
    const float* b1    = (const float*)d_in[4];
    const float* W2    = (const float*)d_in[5];
    const float* b2    = (const float*)d_in[6];
    const float* Wl    = (const float*)d_in[7];
    const float* bl    = (const float*)d_in[8];

    int n = in_sizes[0] / D;
    int E = in_sizes[1] / 2;
    const int* src = ei;
    const int* dst = ei + E;

    void *ph1, *ph2, *phh, *pbh1, *pbl1, *pbh2, *pbl2;
    cudaGetSymbolAddress(&ph1, g_h1);
    cudaGetSymbolAddress(&ph2, g_h2);
    cudaGetSymbolAddress(&phh, g_hh);
    cudaGetSymbolAddress(&pbh1, g_BH1);
    cudaGetSymbolAddress(&pbl1, g_BL1);
    cudaGetSymbolAddress(&pbh2, g_BH2);
    cudaGetSymbolAddress(&pbl2, g_BL2);
    float* h1 = (float*)ph1;
    float* h2 = (float*)ph2;
    __half* hh = (__half*)phh;

    int smem = 3 * 128 * AST * (int)sizeof(float);   // 202752 B
    cudaFuncSetAttribute(k_gemm_mma, cudaFuncAttributeMaxDynamicSharedMemorySize, smem);

    int nblk = (n + 1023) / 1024;       // <= 49 (co-resident for lookback)
    int nblocks8 = (n + 7) / 8;
    int gtiles = (n + 127) / 128;

    // CSR build (4 launches)
    k_init<<<512, 256>>>(W1, W2, n);
    k_hist<<<1024, 256>>>(dst, batch, E, n);
    k_scan<<<nblk, 1024>>>(n, nblk);
    k_permute<<<1024, 256>>>(src, dst, E);

    // Layer 1
    k_gemm_mma<<<gtiles, 256, smem>>>(x, (float*)pbh1, (float*)pbl1, h1, hh, n);
    k_gcn<<<nblocks8, 256>>>(h1, hh, b1, h2, n);

    // Layer 2
    k_gemm_mma<<<gtiles, 256, smem>>>(h2, (float*)pbh2, (float*)pbl2, h1, hh, n);
    k_gcn_pool<<<nblocks8, 256>>>(h1, hh, b2, batch, n);

    // Head
    k_final<<<1, 1024>>>(Wl, bl, (float*)d_out);
}